// round 14
// baseline (speedup 1.0000x reference)
#include <cuda_runtime.h>
#include <stdint.h>

#define BB 16
#define TT 400
#define UPP 512
#define NCH 9                 // H+1
#define NROWS (BB*NCH)        // 144
#define TPRIME (TT*UPP)       // 204800
#define TOTAL (BB*TPRIME)     // 3276800

// per-(row, frame) fractional part of the EXACT exclusive phase prefix (cycles)
__device__ float g_frac[NROWS*TT];

// ---------------------------------------------------------------------------
// Kernel 1: exact exclusive per-frame phase prefixes via int64 fixed point.
// 1 warp per row (b,ch). r*512 cycles is EXACT in units of 2^-33 cycles.
// ---------------------------------------------------------------------------
__global__ void prep_kernel(const float* __restrict__ f0) {
    int row = blockIdx.x;          // 144 blocks of 32 threads
    int lane = threadIdx.x;
    int b = row / NCH, c = row % NCH;
    float kmul = (float)(c + 1);
    const float INV_SR = 2.5e-5f;  // RN(1/40000)

    int t0 = lane * 13;
    int t1 = t0 + 13; if (t1 > TT) t1 = TT;
    if (t0 > TT) t0 = TT;

    long long k[13];
    long long csum = 0;
    #pragma unroll
    for (int u = 0; u < 13; ++u) {
        long long kk = 0;
        int t = t0 + u;
        if (t < t1) {
            float base = __fmul_rn(f0[b*TT + t], INV_SR);
            float r = (c == 0) ? base : __fmul_rn(base, kmul);
            uint32_t ub = __float_as_uint(r);
            int E = (int)((ub >> 23) & 0xFF);
            long long mant = (long long)((ub & 0x7FFFFFu) | 0x800000u);
            int sh = E - 108;                       // r*512*2^33 = mant << sh
            kk = (sh >= 0) ? (mant << sh) : (mant >> (-sh));
        }
        k[u] = kk;
        csum += kk;
    }

    // inclusive warp scan (int64) -> exclusive
    long long pre = csum;
    #pragma unroll
    for (int d = 1; d < 32; d <<= 1) {
        long long v = __shfl_up_sync(0xffffffffu, pre, d);
        if (lane >= d) pre += v;
    }
    pre -= csum;

    const long long MASK33 = (1ll << 33) - 1;
    const float SCALE = 1.1641532182693481e-10f;    // 2^-33
    long long run = pre;
    #pragma unroll
    for (int u = 0; u < 13; ++u) {
        int t = t0 + u;
        if (t < t1)
            g_frac[row*TT + t] = (float)(run & MASK33) * SCALE;
        run += k[u];
    }
}

// ---------------------------------------------------------------------------
// Kernel 2 (fused): grid (TT, BB), 128 threads/block, 4 samples per thread.
// float4 shared per channel {r*2pi, frac*2pi, 0.1*uv*w, 0}; MUFU sin/tanh;
// manually 4-wide-interleaved threefry (ILP=4 through the ALU section);
// float4 stores.
// ---------------------------------------------------------------------------
__device__ __forceinline__ float bits_to_noise(uint32_t bits) {
    float fb = __uint_as_float((bits >> 9) | 0x3f800000u) - 1.0f;   // [0,1)
    const float LO = __uint_as_float(0xBF7FFFFFu);                  // nextafter(-1,0)
    float u = fmaxf(LO, __fadd_rn(__fmul_rn(fb, 2.0f), LO));
    float ww = -__logf(__fmaf_rn(-u, u, 1.0f));     // -log(1-u^2), MUFU.LG2
    float p;
    if (ww < 5.0f) {
        ww -= 2.5f;
        p = 2.81022636e-08f;
        p = fmaf(p, ww, 3.43273939e-07f);
        p = fmaf(p, ww, -3.5233877e-06f);
        p = fmaf(p, ww, -4.39150654e-06f);
        p = fmaf(p, ww, 0.00021858087f);
        p = fmaf(p, ww, -0.00125372503f);
        p = fmaf(p, ww, -0.00417768164f);
        p = fmaf(p, ww, 0.246640727f);
        p = fmaf(p, ww, 1.50140941f);
    } else {
        ww = sqrtf(ww) - 3.0f;
        p = -0.000200214257f;
        p = fmaf(p, ww, 0.000100950558f);
        p = fmaf(p, ww, 0.00134934322f);
        p = fmaf(p, ww, -0.00367342844f);
        p = fmaf(p, ww, 0.00573950773f);
        p = fmaf(p, ww, -0.0076224613f);
        p = fmaf(p, ww, 0.00943887047f);
        p = fmaf(p, ww, 1.00167406f);
        p = fmaf(p, ww, 2.83297682f);
    }
    // 0.003 * sqrt2_f32 * (p*u), scales folded (<=1 ulp vs reference)
    return 0.0042426409f * (p * u);
}

__device__ __forceinline__ float fast_tanh(float x) {
    float r;
    asm("tanh.approx.f32 %0, %1;" : "=f"(r) : "f"(x));
    return r;
}

__device__ __forceinline__ uint32_t rotl(uint32_t v, int s) {
    return (v << s) | (v >> (32 - s));
}

__global__ void __launch_bounds__(128, 16) fused_kernel(
        const float* __restrict__ f0,
        const float* __restrict__ w,
        const float* __restrict__ bias,
        float* __restrict__ out, int parts) {
    int t = blockIdx.x, b = blockIdx.y;
    int f = b * TT + t;            // == f0 flat index
    int tid = threadIdx.x;         // 0..127

    __shared__ float4 sh4[NCH];    // {r*2pi, frac*2pi, 0.1*uv*w, 0}
    __shared__ float sh_b;
    __shared__ float sh_uv;
    if (tid < NCH) {
        const float TWO_PI = 6.2831853071795864769f;
        float base = __fmul_rn(f0[f], 2.5e-5f);
        float r = (tid == 0) ? base : __fmul_rn(base, (float)(tid + 1));
        float uvv = (f0[f] > 0.0f) ? 1.0f : 0.0f;
        sh4[tid] = make_float4(r * TWO_PI,
                               g_frac[(b*NCH + tid)*TT + t] * TWO_PI,
                               0.1f * uvv * w[tid], 0.0f);
        if (tid == 0) { sh_b = bias[0]; sh_uv = uvv; }
    }
    __syncthreads();

    int j0 = tid * 4;
    float fm0 = (float)(j0 + 1);
    float d0 = 0.0f, d1 = 0.0f, d2 = 0.0f, d3 = 0.0f;

    #pragma unroll
    for (int c = 0; c < NCH; ++c) {
        float4 q = sh4[c];                              // one LDS.128 broadcast
        d0 = __fmaf_rn(__sinf(__fmaf_rn(fm0,        q.x, q.y)), q.z, d0);
        d1 = __fmaf_rn(__sinf(__fmaf_rn(fm0 + 1.0f, q.x, q.y)), q.z, d1);
        d2 = __fmaf_rn(__sinf(__fmaf_rn(fm0 + 2.0f, q.x, q.y)), q.z, d2);
        d3 = __fmaf_rn(__sinf(__fmaf_rn(fm0 + 3.0f, q.x, q.y)), q.z, d3);
    }
    float bb2 = sh_b;
    float uvv = sh_uv;
    float4 mg;
    mg.x = fast_tanh(__fadd_rn(d0, bb2));
    mg.y = fast_tanh(__fadd_rn(d1, bb2));
    mg.z = fast_tanh(__fadd_rn(d2, bb2));
    mg.w = fast_tanh(__fadd_rn(d3, bb2));

    int idx = f*UPP + j0;                               // 4-aligned
    *reinterpret_cast<float4*>(out + idx) = mg;
    if (parts >= 2)
        *reinterpret_cast<float4*>(out + TOTAL + idx) = make_float4(uvv, uvv, uvv, uvv);

    if (parts >= 3) {
        // threefry2x32 partitionable, 4 counters interleaved round-by-round
        // for guaranteed ILP=4 through the dependent ALU chains.
        const uint32_t ks0 = 0u, ks1 = 1u, ks2 = 0x1BD11BDBu;
        uint32_t u0 = (uint32_t)idx;
        uint32_t a0 = ks0, a1 = ks0, a2 = ks0, a3 = ks0;
        uint32_t b0 = u0 + ks1, b1 = u0 + 1u + ks1, b2 = u0 + 2u + ks1, b3 = u0 + 3u + ks1;

#define TF4(r) { \
        a0 += b0; b0 = rotl(b0, r); b0 ^= a0; \
        a1 += b1; b1 = rotl(b1, r); b1 ^= a1; \
        a2 += b2; b2 = rotl(b2, r); b2 ^= a2; \
        a3 += b3; b3 = rotl(b3, r); b3 ^= a3; }
#define TF4_KEY(ka, kb) { \
        a0 += (ka); b0 += (kb); a1 += (ka); b1 += (kb); \
        a2 += (ka); b2 += (kb); a3 += (ka); b3 += (kb); }

        TF4(13) TF4(15) TF4(26) TF4(6)
        TF4_KEY(ks1, ks2 + 1u)
        TF4(17) TF4(29) TF4(16) TF4(24)
        TF4_KEY(ks2, ks0 + 2u)
        TF4(13) TF4(15) TF4(26) TF4(6)
        TF4_KEY(ks0, ks1 + 3u)
        TF4(17) TF4(29) TF4(16) TF4(24)
        TF4_KEY(ks1, ks2 + 4u)
        TF4(13) TF4(15) TF4(26) TF4(6)
        TF4_KEY(ks2, ks0 + 5u)
#undef TF4
#undef TF4_KEY

        float4 nz;
        nz.x = bits_to_noise(a0 ^ b0);
        nz.y = bits_to_noise(a1 ^ b1);
        nz.z = bits_to_noise(a2 ^ b2);
        nz.w = bits_to_noise(a3 ^ b3);
        *reinterpret_cast<float4*>(out + 2*TOTAL + idx) = nz;
    }
}

// ---------------------------------------------------------------------------
extern "C" void kernel_launch(void* const* d_in, const int* in_sizes, int n_in,
                              void* d_out, int out_size) {
    const float* f0 = (const float*)d_in[0];
    const float* w  = (const float*)d_in[1];
    const float* b  = (const float*)d_in[2];
    float* out = (float*)d_out;
    int parts = out_size / TOTAL;   // 1: sine_merge, 2: +uv, 3: +noise

    prep_kernel<<<NROWS, 32>>>(f0);
    fused_kernel<<<dim3(TT, BB), 128>>>(f0, w, b, out, parts);
}

// round 15
// speedup vs baseline: 1.0587x; 1.0587x over previous
#include <cuda_runtime.h>
#include <stdint.h>

#define BB 16
#define TT 400
#define UPP 512
#define NCH 9                 // H+1
#define NROWS (BB*NCH)        // 144
#define TPRIME (TT*UPP)       // 204800
#define TOTAL (BB*TPRIME)     // 3276800

// per-(row, frame) fractional part of the EXACT exclusive phase prefix (cycles)
__device__ float g_frac[NROWS*TT];

// ---------------------------------------------------------------------------
// Kernel 1: exact exclusive per-frame phase prefixes via int64 fixed point.
// 128 threads per row: 4 frames/lane + warp shuffle scan + cross-warp scan.
// r*512 cycles is EXACT in units of 2^-33 cycles (33-bit frac field).
// ---------------------------------------------------------------------------
__global__ void prep_kernel(const float* __restrict__ f0) {
    int row = blockIdx.x;          // 144 blocks of 128 threads
    int tid = threadIdx.x;
    int lane = tid & 31, wid = tid >> 5;
    int b = row / NCH, c = row % NCH;
    float kmul = (float)(c + 1);
    const float INV_SR = 2.5e-5f;  // RN(1/40000)

    int t0 = tid * 4;              // 4 frames per thread; threads >= 100 idle-ish

    long long k[4];
    long long csum = 0;
    #pragma unroll
    for (int u = 0; u < 4; ++u) {
        long long kk = 0;
        int t = t0 + u;
        if (t < TT) {
            float base = __fmul_rn(f0[b*TT + t], INV_SR);
            float r = (c == 0) ? base : __fmul_rn(base, kmul);
            uint32_t ub = __float_as_uint(r);
            int E = (int)((ub >> 23) & 0xFF);
            long long mant = (long long)((ub & 0x7FFFFFu) | 0x800000u);
            int sh = E - 108;                       // r*512*2^33 = mant << sh
            kk = (sh >= 0) ? (mant << sh) : (mant >> (-sh));
        }
        k[u] = kk;
        csum += kk;
    }

    // intra-warp inclusive scan (int64)
    long long inc = csum;
    #pragma unroll
    for (int d = 1; d < 32; d <<= 1) {
        long long v = __shfl_up_sync(0xffffffffu, inc, d);
        if (lane >= d) inc += v;
    }
    // cross-warp: publish warp totals, exclusive-add
    __shared__ long long wsum[4];
    if (lane == 31) wsum[wid] = inc;
    __syncthreads();
    long long warp_pre = 0;
    #pragma unroll
    for (int ww = 0; ww < 4; ++ww)
        if (ww < wid) warp_pre += wsum[ww];
    long long run = warp_pre + (inc - csum);        // exclusive prefix for this thread

    const long long MASK33 = (1ll << 33) - 1;
    const float SCALE = 1.1641532182693481e-10f;    // 2^-33
    #pragma unroll
    for (int u = 0; u < 4; ++u) {
        int t = t0 + u;
        if (t < TT)
            g_frac[row*TT + t] = (float)(run & MASK33) * SCALE;
        run += k[u];
    }
}

// ---------------------------------------------------------------------------
// Kernel 2 (fused): grid (TT, BB), 128 threads/block, 4 samples per thread.
// float4 shared per channel {r*2pi, frac*2pi, 0.1*uv*w, 0}; MUFU sin/tanh;
// threefry noise with BRANCHLESS erfinv (FSEL'd coefficients, one FMA chain
// -> same FP sequence per sample as the branched version, no BSSY/BSYNC).
// ---------------------------------------------------------------------------
__device__ __forceinline__ float bits_to_noise(uint32_t bits) {
    float fb = __uint_as_float((bits >> 9) | 0x3f800000u) - 1.0f;   // [0,1)
    const float LO = __uint_as_float(0xBF7FFFFFu);                  // nextafter(-1,0)
    float u = fmaxf(LO, __fadd_rn(__fmul_rn(fb, 2.0f), LO));
    float ww = -__logf(__fmaf_rn(-u, u, 1.0f));     // -log(1-u^2), MUFU.LG2
    bool tail = !(ww < 5.0f);
    float x = tail ? (sqrtf(ww) - 3.0f) : (ww - 2.5f);
    float p =        tail ? -0.000200214257f : 2.81022636e-08f;
    p = fmaf(p, x,   tail ?  0.000100950558f : 3.43273939e-07f);
    p = fmaf(p, x,   tail ?  0.00134934322f  : -3.5233877e-06f);
    p = fmaf(p, x,   tail ? -0.00367342844f  : -4.39150654e-06f);
    p = fmaf(p, x,   tail ?  0.00573950773f  : 0.00021858087f);
    p = fmaf(p, x,   tail ? -0.0076224613f   : -0.00125372503f);
    p = fmaf(p, x,   tail ?  0.00943887047f  : -0.00417768164f);
    p = fmaf(p, x,   tail ?  1.00167406f     : 0.246640727f);
    p = fmaf(p, x,   tail ?  2.83297682f     : 1.50140941f);
    // 0.003 * sqrt2_f32 * (p*u), scales folded (<=1 ulp vs reference)
    return 0.0042426409f * (p * u);
}

__device__ __forceinline__ float fast_tanh(float x) {
    float r;
    asm("tanh.approx.f32 %0, %1;" : "=f"(r) : "f"(x));
    return r;
}

__device__ __forceinline__ uint32_t rotl(uint32_t v, int s) {
    return __funnelshift_l(v, v, s);               // single SHF
}

__global__ void __launch_bounds__(128, 16) fused_kernel(
        const float* __restrict__ f0,
        const float* __restrict__ w,
        const float* __restrict__ bias,
        float* __restrict__ out, int parts) {
    int t = blockIdx.x, b = blockIdx.y;
    int f = b * TT + t;            // == f0 flat index
    int tid = threadIdx.x;         // 0..127

    __shared__ float4 sh4[NCH];    // {r*2pi, frac*2pi, 0.1*uv*w, 0}
    __shared__ float sh_b;
    __shared__ float sh_uv;
    if (tid < NCH) {
        const float TWO_PI = 6.2831853071795864769f;
        float base = __fmul_rn(f0[f], 2.5e-5f);
        float r = (tid == 0) ? base : __fmul_rn(base, (float)(tid + 1));
        float uvv = (f0[f] > 0.0f) ? 1.0f : 0.0f;
        sh4[tid] = make_float4(r * TWO_PI,
                               g_frac[(b*NCH + tid)*TT + t] * TWO_PI,
                               0.1f * uvv * w[tid], 0.0f);
        if (tid == 0) { sh_b = bias[0]; sh_uv = uvv; }
    }
    __syncthreads();

    int j0 = tid * 4;
    float fm0 = (float)(j0 + 1);
    float d0 = 0.0f, d1 = 0.0f, d2 = 0.0f, d3 = 0.0f;

    #pragma unroll
    for (int c = 0; c < NCH; ++c) {
        float4 q = sh4[c];                              // one LDS.128 broadcast
        d0 = __fmaf_rn(__sinf(__fmaf_rn(fm0,        q.x, q.y)), q.z, d0);
        d1 = __fmaf_rn(__sinf(__fmaf_rn(fm0 + 1.0f, q.x, q.y)), q.z, d1);
        d2 = __fmaf_rn(__sinf(__fmaf_rn(fm0 + 2.0f, q.x, q.y)), q.z, d2);
        d3 = __fmaf_rn(__sinf(__fmaf_rn(fm0 + 3.0f, q.x, q.y)), q.z, d3);
    }
    float bb2 = sh_b;
    float uvv = sh_uv;
    float4 mg;
    mg.x = fast_tanh(__fadd_rn(d0, bb2));
    mg.y = fast_tanh(__fadd_rn(d1, bb2));
    mg.z = fast_tanh(__fadd_rn(d2, bb2));
    mg.w = fast_tanh(__fadd_rn(d3, bb2));

    int idx = f*UPP + j0;                               // 4-aligned
    *reinterpret_cast<float4*>(out + idx) = mg;
    if (parts >= 2)
        *reinterpret_cast<float4*>(out + TOTAL + idx) = make_float4(uvv, uvv, uvv, uvv);

    if (parts >= 3) {
        // threefry2x32 partitionable, 4 counters interleaved round-by-round
        const uint32_t ks0 = 0u, ks1 = 1u, ks2 = 0x1BD11BDBu;
        uint32_t u0 = (uint32_t)idx;
        uint32_t a0 = ks0, a1 = ks0, a2 = ks0, a3 = ks0;
        uint32_t b0 = u0 + ks1, b1 = u0 + 1u + ks1, b2 = u0 + 2u + ks1, b3 = u0 + 3u + ks1;

#define TF4(r) { \
        a0 += b0; b0 = rotl(b0, r); b0 ^= a0; \
        a1 += b1; b1 = rotl(b1, r); b1 ^= a1; \
        a2 += b2; b2 = rotl(b2, r); b2 ^= a2; \
        a3 += b3; b3 = rotl(b3, r); b3 ^= a3; }
#define TF4_KEY(ka, kb) { \
        a0 += (ka); b0 += (kb); a1 += (ka); b1 += (kb); \
        a2 += (ka); b2 += (kb); a3 += (ka); b3 += (kb); }

        TF4(13) TF4(15) TF4(26) TF4(6)
        TF4_KEY(ks1, ks2 + 1u)
        TF4(17) TF4(29) TF4(16) TF4(24)
        TF4_KEY(ks2, ks0 + 2u)
        TF4(13) TF4(15) TF4(26) TF4(6)
        TF4_KEY(ks0, ks1 + 3u)
        TF4(17) TF4(29) TF4(16) TF4(24)
        TF4_KEY(ks1, ks2 + 4u)
        TF4(13) TF4(15) TF4(26) TF4(6)
        TF4_KEY(ks2, ks0 + 5u)
#undef TF4
#undef TF4_KEY

        float4 nz;
        nz.x = bits_to_noise(a0 ^ b0);
        nz.y = bits_to_noise(a1 ^ b1);
        nz.z = bits_to_noise(a2 ^ b2);
        nz.w = bits_to_noise(a3 ^ b3);
        *reinterpret_cast<float4*>(out + 2*TOTAL + idx) = nz;
    }
}

// ---------------------------------------------------------------------------
extern "C" void kernel_launch(void* const* d_in, const int* in_sizes, int n_in,
                              void* d_out, int out_size) {
    const float* f0 = (const float*)d_in[0];
    const float* w  = (const float*)d_in[1];
    const float* b  = (const float*)d_in[2];
    float* out = (float*)d_out;
    int parts = out_size / TOTAL;   // 1: sine_merge, 2: +uv, 3: +noise

    prep_kernel<<<NROWS, 128>>>(f0);
    fused_kernel<<<dim3(TT, BB), 128>>>(f0, w, b, out, parts);
}

// round 16
// speedup vs baseline: 1.0908x; 1.0303x over previous
#include <cuda_runtime.h>
#include <stdint.h>

#define BB 16
#define TT 400
#define UPP 512
#define NCH 9                 // H+1
#define NROWS (BB*NCH)        // 144
#define TPRIME (TT*UPP)       // 204800
#define TOTAL (BB*TPRIME)     // 3276800

// per-(row, frame) fractional part of the EXACT exclusive phase prefix (cycles)
__device__ float g_frac[NROWS*TT];

// ---------------------------------------------------------------------------
// Kernel 1: exact exclusive per-frame phase prefixes via int64 fixed point.
// 128 threads per row: 4 frames/lane + warp shuffle scan + cross-warp scan.
// r*512 cycles is EXACT in units of 2^-33 cycles (33-bit frac field).
// Signals dependent launch (PDL) after its g_frac stores.
// ---------------------------------------------------------------------------
__global__ void prep_kernel(const float* __restrict__ f0) {
    int row = blockIdx.x;          // 144 blocks of 128 threads
    int tid = threadIdx.x;
    int lane = tid & 31, wid = tid >> 5;
    int b = row / NCH, c = row % NCH;
    float kmul = (float)(c + 1);
    const float INV_SR = 2.5e-5f;  // RN(1/40000)

    int t0 = tid * 4;              // 4 frames per thread

    long long k[4];
    long long csum = 0;
    #pragma unroll
    for (int u = 0; u < 4; ++u) {
        long long kk = 0;
        int t = t0 + u;
        if (t < TT) {
            float base = __fmul_rn(f0[b*TT + t], INV_SR);
            float r = (c == 0) ? base : __fmul_rn(base, kmul);
            uint32_t ub = __float_as_uint(r);
            int E = (int)((ub >> 23) & 0xFF);
            long long mant = (long long)((ub & 0x7FFFFFu) | 0x800000u);
            int sh = E - 108;                       // r*512*2^33 = mant << sh
            kk = (sh >= 0) ? (mant << sh) : (mant >> (-sh));
        }
        k[u] = kk;
        csum += kk;
    }

    // intra-warp inclusive scan (int64)
    long long inc = csum;
    #pragma unroll
    for (int d = 1; d < 32; d <<= 1) {
        long long v = __shfl_up_sync(0xffffffffu, inc, d);
        if (lane >= d) inc += v;
    }
    // cross-warp: publish warp totals, exclusive-add
    __shared__ long long wsum[4];
    if (lane == 31) wsum[wid] = inc;
    __syncthreads();
    long long warp_pre = 0;
    #pragma unroll
    for (int ww = 0; ww < 4; ++ww)
        if (ww < wid) warp_pre += wsum[ww];
    long long run = warp_pre + (inc - csum);        // exclusive prefix for this thread

    const long long MASK33 = (1ll << 33) - 1;
    const float SCALE = 1.1641532182693481e-10f;    // 2^-33
    #pragma unroll
    for (int u = 0; u < 4; ++u) {
        int t = t0 + u;
        if (t < TT)
            g_frac[row*TT + t] = (float)(run & MASK33) * SCALE;
        run += k[u];
    }
    // PDL: allow the dependent fused kernel to launch; its griddepcontrol.wait
    // guarantees visibility of the g_frac stores above.
    asm volatile("griddepcontrol.launch_dependents;");
}

// ---------------------------------------------------------------------------
// Kernel 2 (fused): grid (TT, BB), 128 threads/block, 4 samples per thread.
// NOISE FIRST (independent of prep; overlaps prep via PDL), then
// griddepcontrol.wait, then sine/uv using g_frac.
// ---------------------------------------------------------------------------
__device__ __forceinline__ float fast_sqrt(float x) {
    float r;
    asm("sqrt.approx.f32 %0, %1;" : "=f"(r) : "f"(x));
    return r;
}

__device__ __forceinline__ float bits_to_noise(uint32_t bits) {
    float fb = __uint_as_float((bits >> 9) | 0x3f800000u) - 1.0f;   // [0,1)
    const float LO = __uint_as_float(0xBF7FFFFFu);                  // nextafter(-1,0)
    float u = fmaxf(LO, __fadd_rn(__fmul_rn(fb, 2.0f), LO));
    float ww = -__logf(__fmaf_rn(-u, u, 1.0f));     // -log(1-u^2), MUFU.LG2
    bool tail = !(ww < 5.0f);
    float x = tail ? (fast_sqrt(ww) - 3.0f) : (ww - 2.5f);
    float p =        tail ? -0.000200214257f : 2.81022636e-08f;
    p = fmaf(p, x,   tail ?  0.000100950558f : 3.43273939e-07f);
    p = fmaf(p, x,   tail ?  0.00134934322f  : -3.5233877e-06f);
    p = fmaf(p, x,   tail ? -0.00367342844f  : -4.39150654e-06f);
    p = fmaf(p, x,   tail ?  0.00573950773f  : 0.00021858087f);
    p = fmaf(p, x,   tail ? -0.0076224613f   : -0.00125372503f);
    p = fmaf(p, x,   tail ?  0.00943887047f  : -0.00417768164f);
    p = fmaf(p, x,   tail ?  1.00167406f     : 0.246640727f);
    p = fmaf(p, x,   tail ?  2.83297682f     : 1.50140941f);
    // 0.003 * sqrt2_f32 * (p*u), scales folded (<=1 ulp vs reference)
    return 0.0042426409f * (p * u);
}

__device__ __forceinline__ float fast_tanh(float x) {
    float r;
    asm("tanh.approx.f32 %0, %1;" : "=f"(r) : "f"(x));
    return r;
}

__device__ __forceinline__ uint32_t rotl(uint32_t v, int s) {
    return __funnelshift_l(v, v, s);               // single SHF
}

__global__ void __launch_bounds__(128, 16) fused_kernel(
        const float* __restrict__ f0,
        const float* __restrict__ w,
        const float* __restrict__ bias,
        float* __restrict__ out, int parts) {
    int t = blockIdx.x, b = blockIdx.y;
    int f = b * TT + t;            // == f0 flat index
    int tid = threadIdx.x;         // 0..127
    int j0 = tid * 4;
    int idx = f*UPP + j0;          // 4-aligned

    // ---- Phase 0: noise (no dependency on prep; overlaps it via PDL) ----
    if (parts >= 3) {
        const uint32_t ks0 = 0u, ks1 = 1u, ks2 = 0x1BD11BDBu;
        uint32_t u0 = (uint32_t)idx;
        uint32_t a0 = ks0, a1 = ks0, a2 = ks0, a3 = ks0;
        uint32_t b0 = u0 + ks1, b1 = u0 + 1u + ks1, b2 = u0 + 2u + ks1, b3 = u0 + 3u + ks1;

#define TF4(r) { \
        a0 += b0; b0 = rotl(b0, r); b0 ^= a0; \
        a1 += b1; b1 = rotl(b1, r); b1 ^= a1; \
        a2 += b2; b2 = rotl(b2, r); b2 ^= a2; \
        a3 += b3; b3 = rotl(b3, r); b3 ^= a3; }
#define TF4_KEY(ka, kb) { \
        a0 += (ka); b0 += (kb); a1 += (ka); b1 += (kb); \
        a2 += (ka); b2 += (kb); a3 += (ka); b3 += (kb); }

        TF4(13) TF4(15) TF4(26) TF4(6)
        TF4_KEY(ks1, ks2 + 1u)
        TF4(17) TF4(29) TF4(16) TF4(24)
        TF4_KEY(ks2, ks0 + 2u)
        TF4(13) TF4(15) TF4(26) TF4(6)
        TF4_KEY(ks0, ks1 + 3u)
        TF4(17) TF4(29) TF4(16) TF4(24)
        TF4_KEY(ks1, ks2 + 4u)
        TF4(13) TF4(15) TF4(26) TF4(6)
        TF4_KEY(ks2, ks0 + 5u)
#undef TF4
#undef TF4_KEY

        float4 nz;
        nz.x = bits_to_noise(a0 ^ b0);
        nz.y = bits_to_noise(a1 ^ b1);
        nz.z = bits_to_noise(a2 ^ b2);
        nz.w = bits_to_noise(a3 ^ b3);
        *reinterpret_cast<float4*>(out + 2*TOTAL + idx) = nz;
    }

    // ---- PDL join: prep's g_frac stores are visible after this ----
    asm volatile("griddepcontrol.wait;" ::: "memory");

    // ---- Phase 1: sine + uv ----
    __shared__ float4 sh4[NCH];    // {r*2pi, frac*2pi, 0.1*uv*w, 0}
    __shared__ float sh_b;
    __shared__ float sh_uv;
    if (tid < NCH) {
        const float TWO_PI = 6.2831853071795864769f;
        float base = __fmul_rn(f0[f], 2.5e-5f);
        float r = (tid == 0) ? base : __fmul_rn(base, (float)(tid + 1));
        float uvv = (f0[f] > 0.0f) ? 1.0f : 0.0f;
        sh4[tid] = make_float4(r * TWO_PI,
                               g_frac[(b*NCH + tid)*TT + t] * TWO_PI,
                               0.1f * uvv * w[tid], 0.0f);
        if (tid == 0) { sh_b = bias[0]; sh_uv = uvv; }
    }
    __syncthreads();

    float fm0 = (float)(j0 + 1);
    float d0 = 0.0f, d1 = 0.0f, d2 = 0.0f, d3 = 0.0f;

    #pragma unroll
    for (int c = 0; c < NCH; ++c) {
        float4 q = sh4[c];                              // one LDS.128 broadcast
        d0 = __fmaf_rn(__sinf(__fmaf_rn(fm0,        q.x, q.y)), q.z, d0);
        d1 = __fmaf_rn(__sinf(__fmaf_rn(fm0 + 1.0f, q.x, q.y)), q.z, d1);
        d2 = __fmaf_rn(__sinf(__fmaf_rn(fm0 + 2.0f, q.x, q.y)), q.z, d2);
        d3 = __fmaf_rn(__sinf(__fmaf_rn(fm0 + 3.0f, q.x, q.y)), q.z, d3);
    }
    float bb2 = sh_b;
    float uvv = sh_uv;
    float4 mg;
    mg.x = fast_tanh(__fadd_rn(d0, bb2));
    mg.y = fast_tanh(__fadd_rn(d1, bb2));
    mg.z = fast_tanh(__fadd_rn(d2, bb2));
    mg.w = fast_tanh(__fadd_rn(d3, bb2));

    *reinterpret_cast<float4*>(out + idx) = mg;
    if (parts >= 2)
        *reinterpret_cast<float4*>(out + TOTAL + idx) = make_float4(uvv, uvv, uvv, uvv);
}

// ---------------------------------------------------------------------------
extern "C" void kernel_launch(void* const* d_in, const int* in_sizes, int n_in,
                              void* d_out, int out_size) {
    const float* f0 = (const float*)d_in[0];
    const float* w  = (const float*)d_in[1];
    const float* b  = (const float*)d_in[2];
    float* out = (float*)d_out;
    int parts = out_size / TOTAL;   // 1: sine_merge, 2: +uv, 3: +noise

    prep_kernel<<<NROWS, 128>>>(f0);

    // PDL: fused may begin (noise phase) before prep completes; the
    // griddepcontrol.wait inside fused orders the g_frac consumption.
    cudaLaunchConfig_t cfg = {};
    cfg.gridDim = dim3(TT, BB);
    cfg.blockDim = dim3(128);
    cfg.dynamicSmemBytes = 0;
    cfg.stream = 0;
    cudaLaunchAttribute attrs[1];
    attrs[0].id = cudaLaunchAttributeProgrammaticStreamSerialization;
    attrs[0].val.programmaticStreamSerializationAllowed = 1;
    cfg.attrs = attrs;
    cfg.numAttrs = 1;
    cudaLaunchKernelEx(&cfg, fused_kernel, f0, w, b, out, parts);
}

// round 17
// speedup vs baseline: 1.1029x; 1.0111x over previous
#include <cuda_runtime.h>
#include <stdint.h>

#define BB 16
#define TT 400
#define UPP 512
#define NCH 9                 // H+1
#define NROWS (BB*NCH)        // 144
#define TPRIME (TT*UPP)       // 204800
#define TOTAL (BB*TPRIME)     // 3276800

// per-(row, frame) fractional part of the EXACT exclusive phase prefix (cycles)
__device__ float g_frac[NROWS*TT];

// ---------------------------------------------------------------------------
// Kernel 1: exact exclusive per-frame phase prefixes via int64 fixed point.
// 128 threads per row; PDL launch_dependents after stores.
// ---------------------------------------------------------------------------
__global__ void prep_kernel(const float* __restrict__ f0) {
    int row = blockIdx.x;          // 144 blocks of 128 threads
    int tid = threadIdx.x;
    int lane = tid & 31, wid = tid >> 5;
    int b = row / NCH, c = row % NCH;
    float kmul = (float)(c + 1);
    const float INV_SR = 2.5e-5f;  // RN(1/40000)

    int t0 = tid * 4;              // 4 frames per thread

    long long k[4];
    long long csum = 0;
    #pragma unroll
    for (int u = 0; u < 4; ++u) {
        long long kk = 0;
        int t = t0 + u;
        if (t < TT) {
            float base = __fmul_rn(f0[b*TT + t], INV_SR);
            float r = (c == 0) ? base : __fmul_rn(base, kmul);
            uint32_t ub = __float_as_uint(r);
            int E = (int)((ub >> 23) & 0xFF);
            long long mant = (long long)((ub & 0x7FFFFFu) | 0x800000u);
            int sh = E - 108;                       // r*512*2^33 = mant << sh
            kk = (sh >= 0) ? (mant << sh) : (mant >> (-sh));
        }
        k[u] = kk;
        csum += kk;
    }

    long long inc = csum;
    #pragma unroll
    for (int d = 1; d < 32; d <<= 1) {
        long long v = __shfl_up_sync(0xffffffffu, inc, d);
        if (lane >= d) inc += v;
    }
    __shared__ long long wsum[4];
    if (lane == 31) wsum[wid] = inc;
    __syncthreads();
    long long warp_pre = 0;
    #pragma unroll
    for (int ww = 0; ww < 4; ++ww)
        if (ww < wid) warp_pre += wsum[ww];
    long long run = warp_pre + (inc - csum);        // exclusive prefix

    const long long MASK33 = (1ll << 33) - 1;
    const float SCALE = 1.1641532182693481e-10f;    // 2^-33
    #pragma unroll
    for (int u = 0; u < 4; ++u) {
        int t = t0 + u;
        if (t < TT)
            g_frac[row*TT + t] = (float)(run & MASK33) * SCALE;
        run += k[u];
    }
    asm volatile("griddepcontrol.launch_dependents;");
}

// ---------------------------------------------------------------------------
// Kernel 2 (fused): noise first (overlaps prep via PDL), then wait, then
// sine/uv. erfinv: main poly unconditional; rare tail (P~3e-4/draw) behind a
// warp-uniform __any_sync guard -> hot path has no FSELs / sqrt.
// ---------------------------------------------------------------------------
__device__ __forceinline__ float fast_sqrt(float x) {
    float r;
    asm("sqrt.approx.f32 %0, %1;" : "=f"(r) : "f"(x));
    return r;
}

__device__ __forceinline__ float fast_tanh(float x) {
    float r;
    asm("tanh.approx.f32 %0, %1;" : "=f"(r) : "f"(x));
    return r;
}

__device__ __forceinline__ uint32_t rotl(uint32_t v, int s) {
    return __funnelshift_l(v, v, s);               // single SHF
}

// uniform + ww from threefry bits (shared prologue of both poly paths)
__device__ __forceinline__ void noise_pre(uint32_t bits, float& u, float& ww) {
    float fb = __uint_as_float((bits >> 9) | 0x3f800000u) - 1.0f;   // [0,1)
    const float LO = __uint_as_float(0xBF7FFFFFu);                  // nextafter(-1,0)
    u = fmaxf(LO, __fadd_rn(__fmul_rn(fb, 2.0f), LO));
    ww = -__logf(__fmaf_rn(-u, u, 1.0f));           // -log(1-u^2), MUFU.LG2
}

__device__ __forceinline__ float noise_main(float u, float ww) {
    float x = ww - 2.5f;
    float p = 2.81022636e-08f;
    p = fmaf(p, x, 3.43273939e-07f);
    p = fmaf(p, x, -3.5233877e-06f);
    p = fmaf(p, x, -4.39150654e-06f);
    p = fmaf(p, x, 0.00021858087f);
    p = fmaf(p, x, -0.00125372503f);
    p = fmaf(p, x, -0.00417768164f);
    p = fmaf(p, x, 0.246640727f);
    p = fmaf(p, x, 1.50140941f);
    return 0.0042426409f * (p * u);   // 0.003*sqrt2 folded
}

__device__ __forceinline__ float noise_tail(float u, float ww) {
    float x = fast_sqrt(ww) - 3.0f;
    float p = -0.000200214257f;
    p = fmaf(p, x, 0.000100950558f);
    p = fmaf(p, x, 0.00134934322f);
    p = fmaf(p, x, -0.00367342844f);
    p = fmaf(p, x, 0.00573950773f);
    p = fmaf(p, x, -0.0076224613f);
    p = fmaf(p, x, 0.00943887047f);
    p = fmaf(p, x, 1.00167406f);
    p = fmaf(p, x, 2.83297682f);
    return 0.0042426409f * (p * u);
}

__global__ void __launch_bounds__(128, 16) fused_kernel(
        const float* __restrict__ f0,
        const float* __restrict__ w,
        const float* __restrict__ bias,
        float* __restrict__ out, int parts) {
    int t = blockIdx.x, b = blockIdx.y;
    int f = b * TT + t;            // == f0 flat index
    int tid = threadIdx.x;         // 0..127
    int j0 = tid * 4;
    int idx = f*UPP + j0;          // 4-aligned

    // ---- Phase 0: noise (independent of prep; overlaps it via PDL) ----
    if (parts >= 3) {
        const uint32_t ks0 = 0u, ks1 = 1u, ks2 = 0x1BD11BDBu;
        uint32_t u0i = (uint32_t)idx;
        uint32_t a0 = ks0, a1 = ks0, a2 = ks0, a3 = ks0;
        uint32_t b0 = u0i + ks1, b1 = u0i + 1u + ks1, b2 = u0i + 2u + ks1, b3 = u0i + 3u + ks1;

#define TF4(r) { \
        a0 += b0; b0 = rotl(b0, r); b0 ^= a0; \
        a1 += b1; b1 = rotl(b1, r); b1 ^= a1; \
        a2 += b2; b2 = rotl(b2, r); b2 ^= a2; \
        a3 += b3; b3 = rotl(b3, r); b3 ^= a3; }
#define TF4_KEY(ka, kb) { \
        a0 += (ka); b0 += (kb); a1 += (ka); b1 += (kb); \
        a2 += (ka); b2 += (kb); a3 += (ka); b3 += (kb); }

        TF4(13) TF4(15) TF4(26) TF4(6)
        TF4_KEY(ks1, ks2 + 1u)
        TF4(17) TF4(29) TF4(16) TF4(24)
        TF4_KEY(ks2, ks0 + 2u)
        TF4(13) TF4(15) TF4(26) TF4(6)
        TF4_KEY(ks0, ks1 + 3u)
        TF4(17) TF4(29) TF4(16) TF4(24)
        TF4_KEY(ks1, ks2 + 4u)
        TF4(13) TF4(15) TF4(26) TF4(6)
        TF4_KEY(ks2, ks0 + 5u)
#undef TF4
#undef TF4_KEY

        float un0, un1, un2, un3, w0, w1, w2, w3;
        noise_pre(a0 ^ b0, un0, w0);
        noise_pre(a1 ^ b1, un1, w1);
        noise_pre(a2 ^ b2, un2, w2);
        noise_pre(a3 ^ b3, un3, w3);

        float4 nz;
        nz.x = noise_main(un0, w0);
        nz.y = noise_main(un1, w1);
        nz.z = noise_main(un2, w2);
        nz.w = noise_main(un3, w3);

        // rare tail: P(any in warp) ~ 4%; warp-uniform guard
        bool mytail = (w0 >= 5.0f) | (w1 >= 5.0f) | (w2 >= 5.0f) | (w3 >= 5.0f);
        if (__any_sync(0xffffffffu, mytail)) {
            if (w0 >= 5.0f) nz.x = noise_tail(un0, w0);
            if (w1 >= 5.0f) nz.y = noise_tail(un1, w1);
            if (w2 >= 5.0f) nz.z = noise_tail(un2, w2);
            if (w3 >= 5.0f) nz.w = noise_tail(un3, w3);
        }
        *reinterpret_cast<float4*>(out + 2*TOTAL + idx) = nz;
    }

    // ---- PDL join: prep's g_frac stores visible after this ----
    asm volatile("griddepcontrol.wait;" ::: "memory");

    // ---- Phase 1: sine + uv ----
    __shared__ float4 sh4[NCH];    // {r*2pi, frac*2pi, 0.1*uv*w, 0}
    __shared__ float sh_b;
    __shared__ float sh_uv;
    if (tid < NCH) {
        const float TWO_PI = 6.2831853071795864769f;
        float base = __fmul_rn(f0[f], 2.5e-5f);
        float r = (tid == 0) ? base : __fmul_rn(base, (float)(tid + 1));
        float uvv = (f0[f] > 0.0f) ? 1.0f : 0.0f;
        sh4[tid] = make_float4(r * TWO_PI,
                               g_frac[(b*NCH + tid)*TT + t] * TWO_PI,
                               0.1f * uvv * w[tid], 0.0f);
        if (tid == 0) { sh_b = bias[0]; sh_uv = uvv; }
    }
    __syncthreads();

    float fm0 = (float)(j0 + 1);
    float d0 = 0.0f, d1 = 0.0f, d2 = 0.0f, d3 = 0.0f;

    #pragma unroll
    for (int c = 0; c < NCH; ++c) {
        float4 q = sh4[c];                              // one LDS.128 broadcast
        d0 = __fmaf_rn(__sinf(__fmaf_rn(fm0,        q.x, q.y)), q.z, d0);
        d1 = __fmaf_rn(__sinf(__fmaf_rn(fm0 + 1.0f, q.x, q.y)), q.z, d1);
        d2 = __fmaf_rn(__sinf(__fmaf_rn(fm0 + 2.0f, q.x, q.y)), q.z, d2);
        d3 = __fmaf_rn(__sinf(__fmaf_rn(fm0 + 3.0f, q.x, q.y)), q.z, d3);
    }
    float bb2 = sh_b;
    float uvv = sh_uv;
    float4 mg;
    mg.x = fast_tanh(__fadd_rn(d0, bb2));
    mg.y = fast_tanh(__fadd_rn(d1, bb2));
    mg.z = fast_tanh(__fadd_rn(d2, bb2));
    mg.w = fast_tanh(__fadd_rn(d3, bb2));

    *reinterpret_cast<float4*>(out + idx) = mg;
    if (parts >= 2)
        *reinterpret_cast<float4*>(out + TOTAL + idx) = make_float4(uvv, uvv, uvv, uvv);
}

// ---------------------------------------------------------------------------
extern "C" void kernel_launch(void* const* d_in, const int* in_sizes, int n_in,
                              void* d_out, int out_size) {
    const float* f0 = (const float*)d_in[0];
    const float* w  = (const float*)d_in[1];
    const float* b  = (const float*)d_in[2];
    float* out = (float*)d_out;
    int parts = out_size / TOTAL;   // 1: sine_merge, 2: +uv, 3: +noise

    prep_kernel<<<NROWS, 128>>>(f0);

    cudaLaunchConfig_t cfg = {};
    cfg.gridDim = dim3(TT, BB);
    cfg.blockDim = dim3(128);
    cfg.dynamicSmemBytes = 0;
    cfg.stream = 0;
    cudaLaunchAttribute attrs[1];
    attrs[0].id = cudaLaunchAttributeProgrammaticStreamSerialization;
    attrs[0].val.programmaticStreamSerializationAllowed = 1;
    cfg.attrs = attrs;
    cfg.numAttrs = 1;
    cudaLaunchKernelEx(&cfg, fused_kernel, f0, w, b, out, parts);
}